// round 11
// baseline (speedup 1.0000x reference)
#include <cuda_runtime.h>
#include <cuda_bf16.h>
#include <cstdint>

#define BB     8
#define HH     64
#define WW     64
#define NPIX   32768
#define DIM    192
#define QKVN   576
#define HEADSB 2
#define HEADD  32
#define KEXT   384        // hi(192) | lo(192) bf16

typedef unsigned long long u64;
typedef unsigned int u32;

// Scratch (device globals: allocation-free rule)
__device__ float         g_q[(size_t)NPIX * DIM];          // pre-scaled q, [pix][192]
__device__ float         g_kv[(size_t)3 * NPIX * 128];     // [branch][pix][k64|v64]
__device__ __nv_bfloat16 g_xe[(size_t)NPIX * KEXT];
__device__ __nv_bfloat16 g_ye[(size_t)NPIX * KEXT];
__device__ __nv_bfloat16 g_wqe[(size_t)QKVN * KEXT];
__device__ __nv_bfloat16 g_wpe[(size_t)DIM * KEXT];

// ---- f32x2 helpers ---------------------------------------------------------
__device__ __forceinline__ void ffma2(u64& d, u64 a, u64 b) {
    asm("fma.rn.f32x2 %0, %1, %2, %0;" : "+l"(d) : "l"(a), "l"(b));
}
__device__ __forceinline__ u64 dup2(float v) {
    u64 r; asm("mov.b64 %0, {%1, %1};" : "=l"(r) : "f"(v)); return r;
}
__device__ __forceinline__ u64 pk2(float lo, float hi) {
    u64 r; asm("mov.b64 %0, {%1, %2};" : "=l"(r) : "f"(lo), "f"(hi)); return r;
}
__device__ __forceinline__ void unpk2(u64 v, float& lo, float& hi) {
    asm("mov.b64 {%0, %1}, %2;" : "=f"(lo), "=f"(hi) : "l"(v));
}
__device__ __forceinline__ u32 sToU32(const void* p) {
    u32 a;
    asm("{ .reg .u64 t; cvta.to.shared.u64 t, %1; cvt.u32.u64 %0, t; }" : "=r"(a) : "l"(p));
    return a;
}

// ---- warp MMA primitives ----------------------------------------------------
#define LDSM4(r, addr) \
    asm volatile("ldmatrix.sync.aligned.m8n8.x4.shared.b16 {%0,%1,%2,%3}, [%4];" \
                 : "=r"((r)[0]), "=r"((r)[1]), "=r"((r)[2]), "=r"((r)[3]) : "r"(addr))

__device__ __forceinline__ void hmma(float* c, const u32* a, u32 b0, u32 b1) {
    asm volatile(
        "mma.sync.aligned.m16n8k16.row.col.f32.bf16.bf16.f32 "
        "{%0,%1,%2,%3}, {%4,%5,%6,%7}, {%8,%9}, {%0,%1,%2,%3};"
        : "+f"(c[0]), "+f"(c[1]), "+f"(c[2]), "+f"(c[3])
        : "r"(a[0]), "r"(a[1]), "r"(a[2]), "r"(a[3]), "r"(b0), "r"(b1));
}

#define CPA16(s, g)  asm volatile("cp.async.cg.shared.global [%0], [%1], 16;" :: "r"(s), "l"(g))
#define CPA_COMMIT() asm volatile("cp.async.commit_group;" ::: "memory")
#define CPA_WAITN(n) asm volatile("cp.async.wait_group %0;" :: "n"(n) : "memory")

// ---------------------------------------------------------------------------
// conv_x: x[b][k][s] fp32 -> g_xe[(b,s)][k]=hi, [192+k]=lo   (32x32 transpose)
// ---------------------------------------------------------------------------
__global__ __launch_bounds__(256) void conv_x(const float* __restrict__ x) {
    __shared__ float t[32][33];
    const int tx = threadIdx.x & 31, ty = threadIdx.x >> 5;
    const int s0 = blockIdx.x * 32, k0 = blockIdx.y * 32, b = blockIdx.z;
    const float* xb = x + ((size_t)b * DIM + k0) * 4096 + s0;
    #pragma unroll
    for (int r = 0; r < 4; r++)
        t[ty + 8 * r][tx] = xb[(size_t)(ty + 8 * r) * 4096 + tx];
    __syncthreads();
    #pragma unroll
    for (int r = 0; r < 4; r++) {
        const int sl = ty + 8 * r;
        const float v = t[tx][sl];
        const __nv_bfloat16 h = __float2bfloat16(v);
        const __nv_bfloat16 l = __float2bfloat16(v - __bfloat162float(h));
        __nv_bfloat16* row = g_xe + (size_t)((b << 12) + s0 + sl) * KEXT;
        row[k0 + tx]       = h;
        row[192 + k0 + tx] = l;
    }
}

__global__ __launch_bounds__(256) void conv_w(const float* __restrict__ wq,
                                              const float* __restrict__ wp) {
    int i = blockIdx.x * 256 + threadIdx.x;
    if (i < QKVN * DIM) {
        const int n = i / DIM, k = i % DIM;
        const float v = wq[i];
        const __nv_bfloat16 h = __float2bfloat16(v);
        const __nv_bfloat16 l = __float2bfloat16(v - __bfloat162float(h));
        g_wqe[(size_t)n * KEXT + k] = h;
        g_wqe[(size_t)n * KEXT + 192 + k] = l;
    } else {
        i -= QKVN * DIM;
        if (i < DIM * DIM) {
            const int n = i / DIM, k = i % DIM;
            const float v = wp[i];
            const __nv_bfloat16 h = __float2bfloat16(v);
            const __nv_bfloat16 l = __float2bfloat16(v - __bfloat162float(h));
            g_wpe[(size_t)n * KEXT + k] = h;
            g_wpe[(size_t)n * KEXT + 192 + k] = l;
        }
    }
}

// ---------------------------------------------------------------------------
// HMMA GEMM, CTA 128x96, 8 warps (4m x 2n, warp 32x48), extended-K split.
// B resident (72 KB); A streamed in 6 octs of 16 KB via 2-slot ring (32 KB).
// 104 KB smem -> 2 CTAs/SM. EPI=0: routed q/kv stores.  EPI=1: CHW out.
// ---------------------------------------------------------------------------
#define MT 128
#define NT 96
#define SM_B 0                      // B: 96 rows x 768 B = 73728
#define SM_A 73728                  // A ring: 2 x 16384
#define SM_TOT 106496

template<int EPI>
__global__ __launch_bounds__(256, 2) void hmma_gemm(const __nv_bfloat16* __restrict__ A,
                                                    const __nv_bfloat16* __restrict__ Bw,
                                                    const float* __restrict__ bias,
                                                    float* __restrict__ outp) {
    extern __shared__ char smem[];
    const u32 sb = sToU32(smem);
    const int tid = threadIdx.x;
    const int wid = tid >> 5, lane = tid & 31;
    const int m0 = blockIdx.x * MT;
    const int n0 = blockIdx.y * NT;

    const __nv_bfloat16* Ab = A + (size_t)m0 * KEXT;
    const __nv_bfloat16* Bb = Bw + (size_t)n0 * KEXT;

    // ---- prologue: B (72 KB, group0), A oct0 (group1), A oct1 (group2)
    #pragma unroll
    for (int i = 0; i < 18; i++) {                       // B: 96 rows x 48 chunks
        const int idx = tid + i * 256;
        const int r = idx / 48, c = idx % 48;
        CPA16(sb + SM_B + r * 768 + ((c ^ (r & 7)) << 4), Bb + (size_t)r * KEXT + c * 8);
    }
    CPA_COMMIT();
    #pragma unroll
    for (int o = 0; o < 2; o++) {                        // A octs: 128 rows x 8 chunks
        #pragma unroll
        for (int i = 0; i < 4; i++) {
            const int idx = tid + i * 256;
            const int r = idx >> 3, c = idx & 7;
            CPA16(sb + SM_A + o * 16384 + r * 128 + ((c ^ (r & 7)) << 4),
                  Ab + (size_t)r * KEXT + (o * 8 + c) * 8);
        }
        CPA_COMMIT();
    }

    const int warpM = (wid >> 1) * 32;
    const int warpN = (wid & 1) * 48;
    const int lr = lane & 15;
    const int lh = lane >> 4;
    const int asw = lr & 7;
    u32 bBase[3]; int bsw[3];
    #pragma unroll
    for (int g = 0; g < 3; g++) {
        const int row = warpN + g * 16 + lr;
        bBase[g] = sb + SM_B + row * 768;
        bsw[g]   = row & 7;
    }

    float acc[2][6][4] = {};

    // ---- 6 stages: st<3 -> A-hi oct st (8 ksteps: B hi oct st, B lo oct st+3)
    //               st>=3 -> A-lo oct st (4 ksteps: B hi oct st-3)
    #pragma unroll
    for (int st = 0; st < 6; st++) {
        if (st < 5) { CPA_WAITN(1); } else { CPA_WAITN(0); }
        __syncthreads();

        const int slot = st & 1;
        const u32 aB = sb + SM_A + slot * 16384 + (warpM + lr) * 128;
        const int nk = (st < 3) ? 8 : 4;
        #pragma unroll
        for (int kk = 0; kk < 8; kk++) {
            if (kk >= nk) break;
            const int boct = (st < 3) ? ((kk < 4) ? st : st + 3) : (st - 3);
            const int al = kk & 3;
            u32 af0[4], af1[4];
            LDSM4(af0, aB + (((al * 2 + lh) ^ asw) << 4));
            LDSM4(af1, aB + 16 * 128 + (((al * 2 + lh) ^ asw) << 4));
            const int bc = boct * 8 + al * 2 + lh;
            u32 bf[3][4];
            #pragma unroll
            for (int g = 0; g < 3; g++)
                LDSM4(bf[g], bBase[g] + ((bc ^ bsw[g]) << 4));
            #pragma unroll
            for (int j = 0; j < 6; j++) {
                const int g = j >> 1, p = j & 1;
                hmma(acc[0][j], af0, bf[g][p], bf[g][p + 2]);
                hmma(acc[1][j], af1, bf[g][p], bf[g][p + 2]);
            }
        }
        __syncthreads();
        if (st < 4) {   // refill slot with A oct st+2
            #pragma unroll
            for (int i = 0; i < 4; i++) {
                const int idx = tid + i * 256;
                const int r = idx >> 3, c = idx & 7;
                CPA16(sb + SM_A + slot * 16384 + r * 128 + ((c ^ (r & 7)) << 4),
                      Ab + (size_t)r * KEXT + ((st + 2) * 8 + c) * 8);
            }
            CPA_COMMIT();
        }
    }

    // ---- epilogue (smem reuse)
    if (EPI == 0) {
        float* Ct = (float*)smem;   // [128][98]
        #pragma unroll
        for (int mt = 0; mt < 2; mt++) {
            #pragma unroll
            for (int j = 0; j < 6; j++) {
                const int rm = warpM + mt * 16 + (lane >> 2);
                const int rn = warpN + j * 8 + (lane & 3) * 2;
                Ct[rm * 98 + rn]           = acc[mt][j][0];
                Ct[rm * 98 + rn + 1]       = acc[mt][j][1];
                Ct[(rm + 8) * 98 + rn]     = acc[mt][j][2];
                Ct[(rm + 8) * 98 + rn + 1] = acc[mt][j][3];
            }
        }
        __syncthreads();
        const float qsc = 0.17677669529663687f;
        #pragma unroll
        for (int i = 0; i < 12; i++) {
            const int idx = tid + i * 256;      // 3072 float4 stores
            const int m = idx / 24, c = (idx % 24) * 4;
            const int n = n0 + c;
            const int br = n / 192, r = n % 192;
            const int sec = r >> 6, off = r & 63;
            const float4 bv = *(const float4*)&bias[n];
            float4 v;
            v.x = Ct[m * 98 + c]     + bv.x;
            v.y = Ct[m * 98 + c + 1] + bv.y;
            v.z = Ct[m * 98 + c + 2] + bv.z;
            v.w = Ct[m * 98 + c + 3] + bv.w;
            const int pix = m0 + m;
            if (sec == 0) {
                v.x *= qsc; v.y *= qsc; v.z *= qsc; v.w *= qsc;
                *(float4*)&g_q[(size_t)pix * DIM + br * 64 + off] = v;
            } else {
                *(float4*)&g_kv[((size_t)(br << 15) + pix) * 128 + (sec - 1) * 64 + off] = v;
            }
        }
    } else {
        float* Ct = (float*)smem;   // [96][132] transposed
        #pragma unroll
        for (int mt = 0; mt < 2; mt++) {
            #pragma unroll
            for (int j = 0; j < 6; j++) {
                const int rn = warpN + j * 8 + (lane & 3) * 2;
                const int rm = warpM + mt * 16 + (lane >> 2);
                Ct[rn * 132 + rm]           = acc[mt][j][0];
                Ct[(rn + 1) * 132 + rm]     = acc[mt][j][1];
                Ct[rn * 132 + rm + 8]       = acc[mt][j][2];
                Ct[(rn + 1) * 132 + rm + 8] = acc[mt][j][3];
            }
        }
        __syncthreads();
        const int b = m0 >> 12, s0 = m0 & 4095;
        float* ob = outp + ((size_t)b * DIM + n0) * 4096 + s0;
        #pragma unroll
        for (int i = 0; i < NT * MT / 256; i++) {
            const int idx = tid + i * 256;
            const int n = idx >> 7, m = idx & 127;
            ob[(size_t)n * 4096 + m] = Ct[n * 132 + m] + bias[n0 + n];
        }
    }
}

// ---------------------------------------------------------------------------
// NATTEN: 8 lanes per (pixel, head), packed g_kv; rpb in smem; k+v rows
// loaded together (MLP 14); max-free softmax. Output split bf16 into g_ye.
// ---------------------------------------------------------------------------
template<int K, int D, int BR>
__device__ __forceinline__ void natten_body(const float* __restrict__ rpb, int blk,
                                            float* __restrict__ srpb) {
    // block-level rpb copy into smem (both heads)
    for (int i = threadIdx.x; i < 2 * (2 * K - 1) * (2 * K - 1); i += 256)
        srpb[i] = rpb[i];
    __syncthreads();

    const int sl   = threadIdx.x & 7;
    const int gid  = (blk * 256 + threadIdx.x) >> 3;
    const int head = gid & 1;
    const int pix  = gid >> 1;
    const int w = pix & 63;
    const int h = (pix >> 6) & 63;
    const int b = pix >> 12;

    const float4 q = *(const float4*)&g_q[(size_t)pix * DIM + BR * 64 + head * HEADD + sl * 4];

    const int gh = h % D, iih = h / D;
    const int Lgh = (HH - gh + D - 1) / D;
    const int sth = min(max(iih - K / 2, 0), Lgh - K);
    const int gw = w % D, iiw = w / D;
    const int Lgw = (WW - gw + D - 1) / D;
    const int stw = min(max(iiw - K / 2, 0), Lgw - K);

    const float* rpbh = srpb + head * (2 * K - 1) * (2 * K - 1)
                       + (sth - iih + K - 1) * (2 * K - 1)
                       + (stw - iiw + K - 1);

    const float* base = g_kv
        + ((size_t)(BR << 15) + (b << 12) + (gh + sth * D) * 64 + (gw + stw * D)) * 128
        + head * HEADD + sl * 4;

    const int strideW = D * 128;
    const int strideH = D * 64 * 128;

    float l = 0.f;
    u64 acc0 = 0, acc1 = 0;

    #pragma unroll
    for (int kh = 0; kh < K; kh++) {
        const float* p = base + (size_t)kh * strideH;
        float sarr[K];
        float4 varr[K];
        #pragma unroll
        for (int kw = 0; kw < K; kw++) {
            const float4 k4 = *(const float4*)(p + (size_t)kw * strideW);
            varr[kw] = *(const float4*)(p + (size_t)kw * strideW + 64);
            sarr[kw] = q.x * k4.x + q.y * k4.y + q.z * k4.z + q.w * k4.w;
        }
        #pragma unroll
        for (int kw = 0; kw < K; kw++) {
            float s = sarr[kw];
            s += __shfl_xor_sync(0xffffffffu, s, 4);
            s += __shfl_xor_sync(0xffffffffu, s, 2);
            s += __shfl_xor_sync(0xffffffffu, s, 1);
            sarr[kw] = __expf(s + rpbh[kh * (2 * K - 1) + kw]);
        }
        #pragma unroll
        for (int kw = 0; kw < K; kw++) {
            const float pr = sarr[kw];
            l += pr;
            const u64 prd = dup2(pr);
            ffma2(acc0, pk2(varr[kw].x, varr[kw].y), prd);
            ffma2(acc1, pk2(varr[kw].z, varr[kw].w), prd);
        }
    }
    const float rinv = __frcp_rn(l);
    float o[4];
    unpk2(acc0, o[0], o[1]);
    unpk2(acc1, o[2], o[3]);

    const int c = BR * 64 + head * HEADD + sl * 4;
    __nv_bfloat16 hi[4], lo[4];
    #pragma unroll
    for (int i = 0; i < 4; i++) {
        const float v = o[i] * rinv;
        hi[i] = __float2bfloat16(v);
        lo[i] = __float2bfloat16(v - __bfloat162float(hi[i]));
    }
    __nv_bfloat16* yr = g_ye + (size_t)pix * KEXT;
    *(u64*)(yr + c)       = *(const u64*)hi;
    *(u64*)(yr + 192 + c) = *(const u64*)lo;
}

#define ABLOCKS (NPIX * HEADSB / 32)   // 2048 blocks per branch

__global__ __launch_bounds__(256) void natten_all(const float* __restrict__ rpb0,
                                                  const float* __restrict__ rpb1,
                                                  const float* __restrict__ rpb2) {
    __shared__ float srpb[338];        // up to 2*13*13
    const int br  = blockIdx.x % 3;    // stripe branches across SMs
    const int idx = blockIdx.x / 3;
    if (br == 0)      natten_body<3, 1, 0>(rpb0, idx, srpb);
    else if (br == 1) natten_body<5, 2, 1>(rpb1, idx, srpb);
    else              natten_body<7, 3, 2>(rpb2, idx, srpb);
}

// ---------------------------------------------------------------------------
extern "C" void kernel_launch(void* const* d_in, const int* in_sizes, int n_in,
                              void* d_out, int out_size) {
    const float* x      = (const float*)d_in[0];
    const float* qkv_w  = (const float*)d_in[1];
    const float* qkv_b  = (const float*)d_in[2];
    const float* proj_w = (const float*)d_in[3];
    const float* proj_b = (const float*)d_in[4];
    const float* rpb0   = (const float*)d_in[5];
    const float* rpb1   = (const float*)d_in[6];
    const float* rpb2   = (const float*)d_in[7];
    float* out = (float*)d_out;

    static bool init_done = false;
    if (!init_done) {
        cudaFuncSetAttribute(hmma_gemm<0>, cudaFuncAttributeMaxDynamicSharedMemorySize, SM_TOT);
        cudaFuncSetAttribute(hmma_gemm<1>, cudaFuncAttributeMaxDynamicSharedMemorySize, SM_TOT);
        init_done = true;
    }

    __nv_bfloat16* xe  = nullptr; cudaGetSymbolAddress((void**)&xe,  g_xe);
    __nv_bfloat16* ye  = nullptr; cudaGetSymbolAddress((void**)&ye,  g_ye);
    __nv_bfloat16* wqe = nullptr; cudaGetSymbolAddress((void**)&wqe, g_wqe);
    __nv_bfloat16* wpe = nullptr; cudaGetSymbolAddress((void**)&wpe, g_wpe);

    conv_x<<<dim3(128, 6, 8), 256>>>(x);
    conv_w<<<576, 256>>>(qkv_w, proj_w);

    hmma_gemm<0><<<dim3(NPIX / MT, QKVN / NT), 256, SM_TOT>>>(xe, wqe, qkv_b, nullptr);

    natten_all<<<3 * ABLOCKS, 256>>>(rpb0, rpb1, rpb2);

    hmma_gemm<1><<<dim3(NPIX / MT, DIM / NT), 256, SM_TOT>>>(ye, wpe, proj_b, out);
}

// round 12
// speedup vs baseline: 1.0546x; 1.0546x over previous
#include <cuda_runtime.h>
#include <cuda_bf16.h>
#include <cstdint>

#define BB     8
#define HH     64
#define WW     64
#define NPIX   32768
#define DIM    192
#define QKVN   576
#define HEADSB 2
#define HEADD  32
#define KEXT   384        // hi(192) | lo(192) bf16

typedef unsigned long long u64;
typedef unsigned int u32;

// Scratch (device globals: allocation-free rule)
__device__ float         g_q[(size_t)NPIX * DIM];          // pre-scaled q, [pix][192]
__device__ float         g_kv[(size_t)3 * NPIX * 128];     // [branch][pix][k64|v64]
__device__ __nv_bfloat16 g_xe[(size_t)NPIX * KEXT];
__device__ __nv_bfloat16 g_ye[(size_t)NPIX * KEXT];
__device__ __nv_bfloat16 g_wqe[(size_t)QKVN * KEXT];
__device__ __nv_bfloat16 g_wpe[(size_t)DIM * KEXT];

// ---- f32x2 helpers ---------------------------------------------------------
__device__ __forceinline__ void ffma2(u64& d, u64 a, u64 b) {
    asm("fma.rn.f32x2 %0, %1, %2, %0;" : "+l"(d) : "l"(a), "l"(b));
}
__device__ __forceinline__ u64 dup2(float v) {
    u64 r; asm("mov.b64 %0, {%1, %1};" : "=l"(r) : "f"(v)); return r;
}
__device__ __forceinline__ u64 pk2(float lo, float hi) {
    u64 r; asm("mov.b64 %0, {%1, %2};" : "=l"(r) : "f"(lo), "f"(hi)); return r;
}
__device__ __forceinline__ void unpk2(u64 v, float& lo, float& hi) {
    asm("mov.b64 {%0, %1}, %2;" : "=f"(lo), "=f"(hi) : "l"(v));
}
__device__ __forceinline__ u32 sToU32(const void* p) {
    u32 a;
    asm("{ .reg .u64 t; cvta.to.shared.u64 t, %1; cvt.u32.u64 %0, t; }" : "=r"(a) : "l"(p));
    return a;
}

// ---- warp MMA primitives ----------------------------------------------------
#define LDSM4(r, addr) \
    asm volatile("ldmatrix.sync.aligned.m8n8.x4.shared.b16 {%0,%1,%2,%3}, [%4];" \
                 : "=r"((r)[0]), "=r"((r)[1]), "=r"((r)[2]), "=r"((r)[3]) : "r"(addr))

__device__ __forceinline__ void hmma(float* c, const u32* a, u32 b0, u32 b1) {
    asm volatile(
        "mma.sync.aligned.m16n8k16.row.col.f32.bf16.bf16.f32 "
        "{%0,%1,%2,%3}, {%4,%5,%6,%7}, {%8,%9}, {%0,%1,%2,%3};"
        : "+f"(c[0]), "+f"(c[1]), "+f"(c[2]), "+f"(c[3])
        : "r"(a[0]), "r"(a[1]), "r"(a[2]), "r"(a[3]), "r"(b0), "r"(b1));
}

#define CPA16(s, g)  asm volatile("cp.async.cg.shared.global [%0], [%1], 16;" :: "r"(s), "l"(g))
#define CPA_COMMIT() asm volatile("cp.async.commit_group;" ::: "memory")
#define CPA_WAITN(n) asm volatile("cp.async.wait_group %0;" :: "n"(n) : "memory")

// ---------------------------------------------------------------------------
// conv_x: x[b][k][s] fp32 -> g_xe[(b,s)][k]=hi, [192+k]=lo   (32x32 transpose)
// ---------------------------------------------------------------------------
__global__ __launch_bounds__(256) void conv_x(const float* __restrict__ x) {
    __shared__ float t[32][33];
    const int tx = threadIdx.x & 31, ty = threadIdx.x >> 5;
    const int s0 = blockIdx.x * 32, k0 = blockIdx.y * 32, b = blockIdx.z;
    const float* xb = x + ((size_t)b * DIM + k0) * 4096 + s0;
    #pragma unroll
    for (int r = 0; r < 4; r++)
        t[ty + 8 * r][tx] = xb[(size_t)(ty + 8 * r) * 4096 + tx];
    __syncthreads();
    #pragma unroll
    for (int r = 0; r < 4; r++) {
        const int sl = ty + 8 * r;
        const float v = t[tx][sl];
        const __nv_bfloat16 h = __float2bfloat16(v);
        const __nv_bfloat16 l = __float2bfloat16(v - __bfloat162float(h));
        __nv_bfloat16* row = g_xe + (size_t)((b << 12) + s0 + sl) * KEXT;
        row[k0 + tx]       = h;
        row[192 + k0 + tx] = l;
    }
}

__global__ __launch_bounds__(256) void conv_w(const float* __restrict__ wq,
                                              const float* __restrict__ wp) {
    int i = blockIdx.x * 256 + threadIdx.x;
    if (i < QKVN * DIM) {
        const int n = i / DIM, k = i % DIM;
        const float v = wq[i];
        const __nv_bfloat16 h = __float2bfloat16(v);
        const __nv_bfloat16 l = __float2bfloat16(v - __bfloat162float(h));
        g_wqe[(size_t)n * KEXT + k] = h;
        g_wqe[(size_t)n * KEXT + 192 + k] = l;
    } else {
        i -= QKVN * DIM;
        if (i < DIM * DIM) {
            const int n = i / DIM, k = i % DIM;
            const float v = wp[i];
            const __nv_bfloat16 h = __float2bfloat16(v);
            const __nv_bfloat16 l = __float2bfloat16(v - __bfloat162float(h));
            g_wpe[(size_t)n * KEXT + k] = h;
            g_wpe[(size_t)n * KEXT + 192 + k] = l;
        }
    }
}

// ---------------------------------------------------------------------------
// HMMA GEMM, CTA 128x64, 8 warps (4m x 2n), extended-K split.
// B resident (48 KB); A streamed in 6 octs of 16 KB via 4-slot ring (64 KB).
// 112 KB smem -> 2 CTAs/SM. EPI=0: routed q/kv stores.  EPI=1: CHW out.
// ---------------------------------------------------------------------------
#define MT 128
#define NT 64
#define SM_B 0                      // B: 64 rows x 768 B = 49152
#define SM_A 49152                  // A ring: 4 x 16384
#define SM_TOT 114688

template<int EPI>
__global__ __launch_bounds__(256, 2) void hmma_gemm(const __nv_bfloat16* __restrict__ A,
                                                    const __nv_bfloat16* __restrict__ Bw,
                                                    const float* __restrict__ bias,
                                                    float* __restrict__ outp) {
    extern __shared__ char smem[];
    const u32 sb = sToU32(smem);
    const int tid = threadIdx.x;
    const int wid = tid >> 5, lane = tid & 31;
    const int m0 = blockIdx.x * MT;
    const int n0 = blockIdx.y * NT;

    const __nv_bfloat16* Ab = A + (size_t)m0 * KEXT;
    const __nv_bfloat16* Bb = Bw + (size_t)n0 * KEXT;

    // ---- prologue: B (48 KB, group0) then A octs 0..3 (16 KB each, groups 1-4)
    #pragma unroll
    for (int i = 0; i < 12; i++) {                       // B: 64 rows x 48 chunks
        const int idx = tid + i * 256;
        const int r = idx / 48, c = idx % 48;
        CPA16(sb + SM_B + r * 768 + ((c ^ (r & 7)) << 4), Bb + (size_t)r * KEXT + c * 8);
    }
    CPA_COMMIT();
    #pragma unroll
    for (int o = 0; o < 4; o++) {                        // A octs: 128 rows x 8 chunks
        #pragma unroll
        for (int i = 0; i < 4; i++) {
            const int idx = tid + i * 256;
            const int r = idx >> 3, c = idx & 7;
            CPA16(sb + SM_A + o * 16384 + r * 128 + ((c ^ (r & 7)) << 4),
                  Ab + (size_t)r * KEXT + (o * 8 + c) * 8);
        }
        CPA_COMMIT();
    }

    const int warpM = (wid >> 1) * 32;
    const int warpN = (wid & 1) * 32;
    const int lr = lane & 15;
    const int lh = lane >> 4;
    const int asw = lr & 7;
    u32 bBase[2]; int bsw[2];
    #pragma unroll
    for (int g = 0; g < 2; g++) {
        const int row = warpN + g * 16 + lr;
        bBase[g] = sb + SM_B + row * 768;
        bsw[g]   = row & 7;
    }

    float acc[2][4][4] = {};

    // ---- 6 stages: st<3 -> A-hi oct st (8 ksteps: B oct st, then st+3)
    //               st>=3 -> A-lo oct st (4 ksteps: B oct st-3)
    // wait schedule for 4-slot ring (groups complete in order):
    //   st 0-2: WAITN(3), st 3: WAITN(2), st 4: WAITN(1), st 5: WAITN(0)
    #pragma unroll
    for (int st = 0; st < 6; st++) {
        if (st < 3) { CPA_WAITN(3); }
        else if (st == 3) { CPA_WAITN(2); }
        else if (st == 4) { CPA_WAITN(1); }
        else { CPA_WAITN(0); }
        __syncthreads();

        const int slot = st & 3;
        const u32 aB = sb + SM_A + slot * 16384 + (warpM + lr) * 128;
        const int nk = (st < 3) ? 8 : 4;
        #pragma unroll
        for (int kk = 0; kk < 8; kk++) {
            if (kk >= nk) break;
            const int boct = (st < 3) ? ((kk < 4) ? st : st + 3) : (st - 3);
            const int al = kk & 3;
            u32 af0[4], af1[4];
            LDSM4(af0, aB + (((al * 2 + lh) ^ asw) << 4));
            LDSM4(af1, aB + 16 * 128 + (((al * 2 + lh) ^ asw) << 4));
            const int bc = boct * 8 + al * 2 + lh;
            u32 bf[2][4];
            #pragma unroll
            for (int g = 0; g < 2; g++)
                LDSM4(bf[g], bBase[g] + ((bc ^ bsw[g]) << 4));
            #pragma unroll
            for (int j = 0; j < 4; j++) {
                const int g = j >> 1, p = j & 1;
                hmma(acc[0][j], af0, bf[g][p], bf[g][p + 2]);
                hmma(acc[1][j], af1, bf[g][p], bf[g][p + 2]);
            }
        }
        __syncthreads();
        if (st < 2) {   // refill freed slot with A oct st+4
            #pragma unroll
            for (int i = 0; i < 4; i++) {
                const int idx = tid + i * 256;
                const int r = idx >> 3, c = idx & 7;
                CPA16(sb + SM_A + slot * 16384 + r * 128 + ((c ^ (r & 7)) << 4),
                      Ab + (size_t)r * KEXT + ((st + 4) * 8 + c) * 8);
            }
            CPA_COMMIT();
        }
    }

    // ---- epilogue (smem reuse)
    if (EPI == 0) {
        float* Ct = (float*)smem;   // [128][68]
        #pragma unroll
        for (int mt = 0; mt < 2; mt++) {
            #pragma unroll
            for (int j = 0; j < 4; j++) {
                const int rm = warpM + mt * 16 + (lane >> 2);
                const int rn = warpN + j * 8 + (lane & 3) * 2;
                Ct[rm * 68 + rn]           = acc[mt][j][0];
                Ct[rm * 68 + rn + 1]       = acc[mt][j][1];
                Ct[(rm + 8) * 68 + rn]     = acc[mt][j][2];
                Ct[(rm + 8) * 68 + rn + 1] = acc[mt][j][3];
            }
        }
        __syncthreads();
        // whole 64-wide tile maps to one section: q (sec 0), k (1), or v (2)
        const int br = n0 / 192, rr = n0 % 192, sec = rr >> 6;
        const float qsc = (sec == 0) ? 0.17677669529663687f : 1.0f;
        #pragma unroll
        for (int i = 0; i < 8; i++) {
            const int idx = tid + i * 256;          // 2048 float4 stores
            const int m = idx >> 4, c = (idx & 15) * 4;
            const float4 bv = *(const float4*)&bias[n0 + c];
            float4 v;
            v.x = (Ct[m * 68 + c]     + bv.x) * qsc;
            v.y = (Ct[m * 68 + c + 1] + bv.y) * qsc;
            v.z = (Ct[m * 68 + c + 2] + bv.z) * qsc;
            v.w = (Ct[m * 68 + c + 3] + bv.w) * qsc;
            const int pix = m0 + m;
            if (sec == 0)
                *(float4*)&g_q[(size_t)pix * DIM + br * 64 + c] = v;
            else
                *(float4*)&g_kv[((size_t)(br << 15) + pix) * 128 + (sec - 1) * 64 + c] = v;
        }
    } else {
        float* Ct = (float*)smem;   // [64][132] transposed
        #pragma unroll
        for (int mt = 0; mt < 2; mt++) {
            #pragma unroll
            for (int j = 0; j < 4; j++) {
                const int rn = warpN + j * 8 + (lane & 3) * 2;
                const int rm = warpM + mt * 16 + (lane >> 2);
                Ct[rn * 132 + rm]           = acc[mt][j][0];
                Ct[(rn + 1) * 132 + rm]     = acc[mt][j][1];
                Ct[rn * 132 + rm + 8]       = acc[mt][j][2];
                Ct[(rn + 1) * 132 + rm + 8] = acc[mt][j][3];
            }
        }
        __syncthreads();
        const int b = m0 >> 12, s0 = m0 & 4095;
        float* ob = outp + ((size_t)b * DIM + n0) * 4096 + s0;
        #pragma unroll
        for (int i = 0; i < 32; i++) {
            const int idx = tid + i * 256;
            const int n = idx >> 7, m = idx & 127;
            ob[(size_t)n * 4096 + m] = Ct[n * 132 + m] + bias[n0 + n];
        }
    }
}

// ---------------------------------------------------------------------------
// NATTEN (R11 body): 8 lanes per (pixel, head), packed g_kv; rpb in smem;
// k+v rows loaded together; max-free softmax. Output split bf16 into g_ye.
// ---------------------------------------------------------------------------
template<int K, int D, int BR>
__device__ __forceinline__ void natten_body(const float* __restrict__ rpb, int blk,
                                            float* __restrict__ srpb) {
    for (int i = threadIdx.x; i < 2 * (2 * K - 1) * (2 * K - 1); i += 256)
        srpb[i] = rpb[i];
    __syncthreads();

    const int sl   = threadIdx.x & 7;
    const int gid  = (blk * 256 + threadIdx.x) >> 3;
    const int head = gid & 1;
    const int pix  = gid >> 1;
    const int w = pix & 63;
    const int h = (pix >> 6) & 63;
    const int b = pix >> 12;

    const float4 q = *(const float4*)&g_q[(size_t)pix * DIM + BR * 64 + head * HEADD + sl * 4];

    const int gh = h % D, iih = h / D;
    const int Lgh = (HH - gh + D - 1) / D;
    const int sth = min(max(iih - K / 2, 0), Lgh - K);
    const int gw = w % D, iiw = w / D;
    const int Lgw = (WW - gw + D - 1) / D;
    const int stw = min(max(iiw - K / 2, 0), Lgw - K);

    const float* rpbh = srpb + head * (2 * K - 1) * (2 * K - 1)
                       + (sth - iih + K - 1) * (2 * K - 1)
                       + (stw - iiw + K - 1);

    const float* base = g_kv
        + ((size_t)(BR << 15) + (b << 12) + (gh + sth * D) * 64 + (gw + stw * D)) * 128
        + head * HEADD + sl * 4;

    const int strideW = D * 128;
    const int strideH = D * 64 * 128;

    float l = 0.f;
    u64 acc0 = 0, acc1 = 0;

    #pragma unroll
    for (int kh = 0; kh < K; kh++) {
        const float* p = base + (size_t)kh * strideH;
        float sarr[K];
        float4 varr[K];
        #pragma unroll
        for (int kw = 0; kw < K; kw++) {
            const float4 k4 = *(const float4*)(p + (size_t)kw * strideW);
            varr[kw] = *(const float4*)(p + (size_t)kw * strideW + 64);
            sarr[kw] = q.x * k4.x + q.y * k4.y + q.z * k4.z + q.w * k4.w;
        }
        #pragma unroll
        for (int kw = 0; kw < K; kw++) {
            float s = sarr[kw];
            s += __shfl_xor_sync(0xffffffffu, s, 4);
            s += __shfl_xor_sync(0xffffffffu, s, 2);
            s += __shfl_xor_sync(0xffffffffu, s, 1);
            sarr[kw] = __expf(s + rpbh[kh * (2 * K - 1) + kw]);
        }
        #pragma unroll
        for (int kw = 0; kw < K; kw++) {
            const float pr = sarr[kw];
            l += pr;
            const u64 prd = dup2(pr);
            ffma2(acc0, pk2(varr[kw].x, varr[kw].y), prd);
            ffma2(acc1, pk2(varr[kw].z, varr[kw].w), prd);
        }
    }
    const float rinv = __frcp_rn(l);
    float o[4];
    unpk2(acc0, o[0], o[1]);
    unpk2(acc1, o[2], o[3]);

    const int c = BR * 64 + head * HEADD + sl * 4;
    __nv_bfloat16 hi[4], lo[4];
    #pragma unroll
    for (int i = 0; i < 4; i++) {
        const float v = o[i] * rinv;
        hi[i] = __float2bfloat16(v);
        lo[i] = __float2bfloat16(v - __bfloat162float(hi[i]));
    }
    __nv_bfloat16* yr = g_ye + (size_t)pix * KEXT;
    *(u64*)(yr + c)       = *(const u64*)hi;
    *(u64*)(yr + 192 + c) = *(const u64*)lo;
}

#define ABLOCKS (NPIX * HEADSB / 32)   // 2048 blocks per branch

__global__ __launch_bounds__(256) void natten_all(const float* __restrict__ rpb0,
                                                  const float* __restrict__ rpb1,
                                                  const float* __restrict__ rpb2) {
    __shared__ float srpb[338];        // up to 2*13*13
    const int br  = blockIdx.x % 3;    // stripe branches across SMs
    const int idx = blockIdx.x / 3;
    if (br == 0)      natten_body<3, 1, 0>(rpb0, idx, srpb);
    else if (br == 1) natten_body<5, 2, 1>(rpb1, idx, srpb);
    else              natten_body<7, 3, 2>(rpb2, idx, srpb);
}

// ---------------------------------------------------------------------------
extern "C" void kernel_launch(void* const* d_in, const int* in_sizes, int n_in,
                              void* d_out, int out_size) {
    const float* x      = (const float*)d_in[0];
    const float* qkv_w  = (const float*)d_in[1];
    const float* qkv_b  = (const float*)d_in[2];
    const float* proj_w = (const float*)d_in[3];
    const float* proj_b = (const float*)d_in[4];
    const float* rpb0   = (const float*)d_in[5];
    const float* rpb1   = (const float*)d_in[6];
    const float* rpb2   = (const float*)d_in[7];
    float* out = (float*)d_out;

    static bool init_done = false;
    if (!init_done) {
        cudaFuncSetAttribute(hmma_gemm<0>, cudaFuncAttributeMaxDynamicSharedMemorySize, SM_TOT);
        cudaFuncSetAttribute(hmma_gemm<1>, cudaFuncAttributeMaxDynamicSharedMemorySize, SM_TOT);
        init_done = true;
    }

    __nv_bfloat16* xe  = nullptr; cudaGetSymbolAddress((void**)&xe,  g_xe);
    __nv_bfloat16* ye  = nullptr; cudaGetSymbolAddress((void**)&ye,  g_ye);
    __nv_bfloat16* wqe = nullptr; cudaGetSymbolAddress((void**)&wqe, g_wqe);
    __nv_bfloat16* wpe = nullptr; cudaGetSymbolAddress((void**)&wpe, g_wpe);

    conv_x<<<dim3(128, 6, 8), 256>>>(x);
    conv_w<<<576, 256>>>(qkv_w, proj_w);

    hmma_gemm<0><<<dim3(NPIX / MT, QKVN / NT), 256, SM_TOT>>>(xe, wqe, qkv_b, nullptr);

    natten_all<<<3 * ABLOCKS, 256>>>(rpb0, rpb1, rpb2);

    hmma_gemm<1><<<dim3(NPIX / MT, DIM / NT), 256, SM_TOT>>>(ye, wpe, proj_b, out);
}

// round 13
// speedup vs baseline: 1.1542x; 1.0945x over previous
#include <cuda_runtime.h>
#include <cuda_bf16.h>
#include <cuda_fp16.h>
#include <cstdint>

#define BB     8
#define HH     64
#define WW     64
#define NPIX   32768
#define DIM    192
#define QKVN   576
#define HEADSB 2
#define HEADD  32
#define KEXT   384        // hi(192) | lo(192) bf16

typedef unsigned long long u64;
typedef unsigned int u32;

// Scratch (device globals: allocation-free rule)
__device__ float         g_q[(size_t)NPIX * DIM];          // pre-scaled q, [pix][192]
__device__ float         g_k[(size_t)3 * NPIX * 64];       // [branch][pix][64] fp32
__device__ __half        g_v[(size_t)3 * NPIX * 64];       // [branch][pix][64] fp16
__device__ __nv_bfloat16 g_xe[(size_t)NPIX * KEXT];
__device__ __nv_bfloat16 g_ye[(size_t)NPIX * KEXT];
__device__ __nv_bfloat16 g_wqe[(size_t)QKVN * KEXT];
__device__ __nv_bfloat16 g_wpe[(size_t)DIM * KEXT];

// ---- f32x2 helpers ---------------------------------------------------------
__device__ __forceinline__ void ffma2(u64& d, u64 a, u64 b) {
    asm("fma.rn.f32x2 %0, %1, %2, %0;" : "+l"(d) : "l"(a), "l"(b));
}
__device__ __forceinline__ u64 dup2(float v) {
    u64 r; asm("mov.b64 %0, {%1, %1};" : "=l"(r) : "f"(v)); return r;
}
__device__ __forceinline__ u64 pk2(float lo, float hi) {
    u64 r; asm("mov.b64 %0, {%1, %2};" : "=l"(r) : "f"(lo), "f"(hi)); return r;
}
__device__ __forceinline__ void unpk2(u64 v, float& lo, float& hi) {
    asm("mov.b64 {%0, %1}, %2;" : "=f"(lo), "=f"(hi) : "l"(v));
}
__device__ __forceinline__ u32 sToU32(const void* p) {
    u32 a;
    asm("{ .reg .u64 t; cvta.to.shared.u64 t, %1; cvt.u32.u64 %0, t; }" : "=r"(a) : "l"(p));
    return a;
}

// ---- warp MMA primitives ----------------------------------------------------
#define LDSM4(r, addr) \
    asm volatile("ldmatrix.sync.aligned.m8n8.x4.shared.b16 {%0,%1,%2,%3}, [%4];" \
                 : "=r"((r)[0]), "=r"((r)[1]), "=r"((r)[2]), "=r"((r)[3]) : "r"(addr))

__device__ __forceinline__ void hmma(float* c, const u32* a, u32 b0, u32 b1) {
    asm volatile(
        "mma.sync.aligned.m16n8k16.row.col.f32.bf16.bf16.f32 "
        "{%0,%1,%2,%3}, {%4,%5,%6,%7}, {%8,%9}, {%0,%1,%2,%3};"
        : "+f"(c[0]), "+f"(c[1]), "+f"(c[2]), "+f"(c[3])
        : "r"(a[0]), "r"(a[1]), "r"(a[2]), "r"(a[3]), "r"(b0), "r"(b1));
}

#define CPA16(s, g)  asm volatile("cp.async.cg.shared.global [%0], [%1], 16;" :: "r"(s), "l"(g))
#define CPA_COMMIT() asm volatile("cp.async.commit_group;" ::: "memory")
#define CPA_WAITN(n) asm volatile("cp.async.wait_group %0;" :: "n"(n) : "memory")

// ---------------------------------------------------------------------------
// conv_all: merged conv_x (blocks 0..6143) + conv_w (blocks 6144..6719)
// ---------------------------------------------------------------------------
__global__ __launch_bounds__(256) void conv_all(const float* __restrict__ x,
                                                const float* __restrict__ wq,
                                                const float* __restrict__ wp) {
    const int bb = blockIdx.x;
    if (bb < 6144) {
        __shared__ float t[32][33];
        const int tx = threadIdx.x & 31, ty = threadIdx.x >> 5;
        const int s0 = (bb & 127) * 32;
        const int k0 = ((bb >> 7) % 6) * 32;
        const int b  = bb / 768;
        const float* xb = x + ((size_t)b * DIM + k0) * 4096 + s0;
        #pragma unroll
        for (int r = 0; r < 4; r++)
            t[ty + 8 * r][tx] = xb[(size_t)(ty + 8 * r) * 4096 + tx];
        __syncthreads();
        #pragma unroll
        for (int r = 0; r < 4; r++) {
            const int sl = ty + 8 * r;
            const float v = t[tx][sl];
            const __nv_bfloat16 h = __float2bfloat16(v);
            const __nv_bfloat16 l = __float2bfloat16(v - __bfloat162float(h));
            __nv_bfloat16* row = g_xe + (size_t)((b << 12) + s0 + sl) * KEXT;
            row[k0 + tx]       = h;
            row[192 + k0 + tx] = l;
        }
    } else {
        int i = (bb - 6144) * 256 + threadIdx.x;
        if (i < QKVN * DIM) {
            const int n = i / DIM, k = i % DIM;
            const float v = wq[i];
            const __nv_bfloat16 h = __float2bfloat16(v);
            const __nv_bfloat16 l = __float2bfloat16(v - __bfloat162float(h));
            g_wqe[(size_t)n * KEXT + k] = h;
            g_wqe[(size_t)n * KEXT + 192 + k] = l;
        } else {
            i -= QKVN * DIM;
            if (i < DIM * DIM) {
                const int n = i / DIM, k = i % DIM;
                const float v = wp[i];
                const __nv_bfloat16 h = __float2bfloat16(v);
                const __nv_bfloat16 l = __float2bfloat16(v - __bfloat162float(h));
                g_wpe[(size_t)n * KEXT + k] = h;
                g_wpe[(size_t)n * KEXT + 192 + k] = l;
            }
        }
    }
}

// ---------------------------------------------------------------------------
// HMMA GEMM, CTA 128x64, 8 warps (4m x 2n), extended-K split.
// B resident (48 KB); A streamed in 6 octs of 16 KB via 4-slot ring (64 KB).
// 112 KB smem -> 2 CTAs/SM. EPI=0: routed q/k/v stores.  EPI=1: CHW out.
// ---------------------------------------------------------------------------
#define MT 128
#define NT 64
#define SM_B 0                      // B: 64 rows x 768 B = 49152
#define SM_A 49152                  // A ring: 4 x 16384
#define SM_TOT 114688

template<int EPI>
__global__ __launch_bounds__(256, 2) void hmma_gemm(const __nv_bfloat16* __restrict__ A,
                                                    const __nv_bfloat16* __restrict__ Bw,
                                                    const float* __restrict__ bias,
                                                    float* __restrict__ outp) {
    extern __shared__ char smem[];
    const u32 sb = sToU32(smem);
    const int tid = threadIdx.x;
    const int wid = tid >> 5, lane = tid & 31;
    const int m0 = blockIdx.x * MT;
    const int n0 = blockIdx.y * NT;

    const __nv_bfloat16* Ab = A + (size_t)m0 * KEXT;
    const __nv_bfloat16* Bb = Bw + (size_t)n0 * KEXT;

    // ---- prologue: B (48 KB, group0) then A octs 0..3 (16 KB each, groups 1-4)
    #pragma unroll
    for (int i = 0; i < 12; i++) {                       // B: 64 rows x 48 chunks
        const int idx = tid + i * 256;
        const int r = idx / 48, c = idx % 48;
        CPA16(sb + SM_B + r * 768 + ((c ^ (r & 7)) << 4), Bb + (size_t)r * KEXT + c * 8);
    }
    CPA_COMMIT();
    #pragma unroll
    for (int o = 0; o < 4; o++) {                        // A octs: 128 rows x 8 chunks
        #pragma unroll
        for (int i = 0; i < 4; i++) {
            const int idx = tid + i * 256;
            const int r = idx >> 3, c = idx & 7;
            CPA16(sb + SM_A + o * 16384 + r * 128 + ((c ^ (r & 7)) << 4),
                  Ab + (size_t)r * KEXT + (o * 8 + c) * 8);
        }
        CPA_COMMIT();
    }

    const int warpM = (wid >> 1) * 32;
    const int warpN = (wid & 1) * 32;
    const int lr = lane & 15;
    const int lh = lane >> 4;
    const int asw = lr & 7;
    u32 bBase[2]; int bsw[2];
    #pragma unroll
    for (int g = 0; g < 2; g++) {
        const int row = warpN + g * 16 + lr;
        bBase[g] = sb + SM_B + row * 768;
        bsw[g]   = row & 7;
    }

    float acc[2][4][4] = {};

    #pragma unroll
    for (int st = 0; st < 6; st++) {
        if (st < 3) { CPA_WAITN(3); }
        else if (st == 3) { CPA_WAITN(2); }
        else if (st == 4) { CPA_WAITN(1); }
        else { CPA_WAITN(0); }
        __syncthreads();

        const int slot = st & 3;
        const u32 aB = sb + SM_A + slot * 16384 + (warpM + lr) * 128;
        const int nk = (st < 3) ? 8 : 4;
        #pragma unroll
        for (int kk = 0; kk < 8; kk++) {
            if (kk >= nk) break;
            const int boct = (st < 3) ? ((kk < 4) ? st : st + 3) : (st - 3);
            const int al = kk & 3;
            u32 af0[4], af1[4];
            LDSM4(af0, aB + (((al * 2 + lh) ^ asw) << 4));
            LDSM4(af1, aB + 16 * 128 + (((al * 2 + lh) ^ asw) << 4));
            const int bc = boct * 8 + al * 2 + lh;
            u32 bf[2][4];
            #pragma unroll
            for (int g = 0; g < 2; g++)
                LDSM4(bf[g], bBase[g] + ((bc ^ bsw[g]) << 4));
            #pragma unroll
            for (int j = 0; j < 4; j++) {
                const int g = j >> 1, p = j & 1;
                hmma(acc[0][j], af0, bf[g][p], bf[g][p + 2]);
                hmma(acc[1][j], af1, bf[g][p], bf[g][p + 2]);
            }
        }
        __syncthreads();
        if (st < 2) {
            #pragma unroll
            for (int i = 0; i < 4; i++) {
                const int idx = tid + i * 256;
                const int r = idx >> 3, c = idx & 7;
                CPA16(sb + SM_A + slot * 16384 + r * 128 + ((c ^ (r & 7)) << 4),
                      Ab + (size_t)r * KEXT + ((st + 4) * 8 + c) * 8);
            }
            CPA_COMMIT();
        }
    }

    // ---- epilogue (smem reuse)
    if (EPI == 0) {
        float* Ct = (float*)smem;   // [128][68]
        #pragma unroll
        for (int mt = 0; mt < 2; mt++) {
            #pragma unroll
            for (int j = 0; j < 4; j++) {
                const int rm = warpM + mt * 16 + (lane >> 2);
                const int rn = warpN + j * 8 + (lane & 3) * 2;
                Ct[rm * 68 + rn]           = acc[mt][j][0];
                Ct[rm * 68 + rn + 1]       = acc[mt][j][1];
                Ct[(rm + 8) * 68 + rn]     = acc[mt][j][2];
                Ct[(rm + 8) * 68 + rn + 1] = acc[mt][j][3];
            }
        }
        __syncthreads();
        // whole 64-wide tile maps to one section: q (sec 0), k (1), or v (2)
        const int br = n0 / 192, rr = n0 % 192, sec = rr >> 6;
        #pragma unroll
        for (int i = 0; i < 8; i++) {
            const int idx = tid + i * 256;          // 2048 stores
            const int m = idx >> 4, c = (idx & 15) * 4;
            const float4 bv = *(const float4*)&bias[n0 + c];
            float4 v;
            v.x = Ct[m * 68 + c]     + bv.x;
            v.y = Ct[m * 68 + c + 1] + bv.y;
            v.z = Ct[m * 68 + c + 2] + bv.z;
            v.w = Ct[m * 68 + c + 3] + bv.w;
            const size_t pix = m0 + m;
            if (sec == 0) {
                const float qsc = 0.17677669529663687f;
                v.x *= qsc; v.y *= qsc; v.z *= qsc; v.w *= qsc;
                *(float4*)&g_q[pix * DIM + br * 64 + c] = v;
            } else if (sec == 1) {
                *(float4*)&g_k[((size_t)(br << 15) + pix) * 64 + c] = v;
            } else {
                __half2 h0 = __float22half2_rn(make_float2(v.x, v.y));
                __half2 h1 = __float22half2_rn(make_float2(v.z, v.w));
                __half2* vp = (__half2*)&g_v[((size_t)(br << 15) + pix) * 64 + c];
                vp[0] = h0; vp[1] = h1;
            }
        }
    } else {
        float* Ct = (float*)smem;   // [64][132] transposed
        #pragma unroll
        for (int mt = 0; mt < 2; mt++) {
            #pragma unroll
            for (int j = 0; j < 4; j++) {
                const int rn = warpN + j * 8 + (lane & 3) * 2;
                const int rm = warpM + mt * 16 + (lane >> 2);
                Ct[rn * 132 + rm]           = acc[mt][j][0];
                Ct[(rn + 1) * 132 + rm]     = acc[mt][j][1];
                Ct[rn * 132 + rm + 8]       = acc[mt][j][2];
                Ct[(rn + 1) * 132 + rm + 8] = acc[mt][j][3];
            }
        }
        __syncthreads();
        const int b = m0 >> 12, s0 = m0 & 4095;
        float* ob = outp + ((size_t)b * DIM + n0) * 4096 + s0;
        #pragma unroll
        for (int i = 0; i < 32; i++) {
            const int idx = tid + i * 256;
            const int n = idx >> 7, m = idx & 127;
            ob[(size_t)n * 4096 + m] = Ct[n * 132 + m] + bias[n0 + n];
        }
    }
}

// ---------------------------------------------------------------------------
// NATTEN: 8 lanes per (pixel, head); k fp32 (g_k), v fp16 (g_v); rpb in smem;
// k+v rows loaded together; max-free softmax. Output split bf16 into g_ye.
// ---------------------------------------------------------------------------
template<int K, int D, int BR>
__device__ __forceinline__ void natten_body(const float* __restrict__ rpb, int blk,
                                            float* __restrict__ srpb) {
    for (int i = threadIdx.x; i < 2 * (2 * K - 1) * (2 * K - 1); i += 256)
        srpb[i] = rpb[i];
    __syncthreads();

    const int sl   = threadIdx.x & 7;
    const int gid  = (blk * 256 + threadIdx.x) >> 3;
    const int head = gid & 1;
    const int pix  = gid >> 1;
    const int w = pix & 63;
    const int h = (pix >> 6) & 63;
    const int b = pix >> 12;

    const float4 q = *(const float4*)&g_q[(size_t)pix * DIM + BR * 64 + head * HEADD + sl * 4];

    const int gh = h % D, iih = h / D;
    const int Lgh = (HH - gh + D - 1) / D;
    const int sth = min(max(iih - K / 2, 0), Lgh - K);
    const int gw = w % D, iiw = w / D;
    const int Lgw = (WW - gw + D - 1) / D;
    const int stw = min(max(iiw - K / 2, 0), Lgw - K);

    const float* rpbh = srpb + head * (2 * K - 1) * (2 * K - 1)
                       + (sth - iih + K - 1) * (2 * K - 1)
                       + (stw - iiw + K - 1);

    const size_t nb0 = (size_t)(BR << 15) + (b << 12) + (gh + sth * D) * 64 + (gw + stw * D);
    const float*  kbase = g_k + nb0 * 64 + head * HEADD + sl * 4;
    const __half* vbase = g_v + nb0 * 64 + head * HEADD + sl * 4;

    const int strideWk = D * 64;            // elems per kw step (fp32 & fp16 same count)
    const int strideHk = D * 64 * 64;

    float l = 0.f;
    u64 acc0 = 0, acc1 = 0;

    #pragma unroll
    for (int kh = 0; kh < K; kh++) {
        const float*  pk = kbase + (size_t)kh * strideHk;
        const __half* pv = vbase + (size_t)kh * strideHk;
        float sarr[K];
        u64 varr[K];                        // 4 halves each
        #pragma unroll
        for (int kw = 0; kw < K; kw++) {
            const float4 k4 = *(const float4*)(pk + (size_t)kw * strideWk);
            varr[kw] = *(const u64*)(pv + (size_t)kw * strideWk);
            sarr[kw] = q.x * k4.x + q.y * k4.y + q.z * k4.z + q.w * k4.w;
        }
        #pragma unroll
        for (int kw = 0; kw < K; kw++) {
            float s = sarr[kw];
            s += __shfl_xor_sync(0xffffffffu, s, 4);
            s += __shfl_xor_sync(0xffffffffu, s, 2);
            s += __shfl_xor_sync(0xffffffffu, s, 1);
            sarr[kw] = __expf(s + rpbh[kh * (2 * K - 1) + kw]);
        }
        #pragma unroll
        for (int kw = 0; kw < K; kw++) {
            const float pr = sarr[kw];
            l += pr;
            const u64 prd = dup2(pr);
            const __half2* vh = (const __half2*)&varr[kw];
            const float2 f01 = __half22float2(vh[0]);
            const float2 f23 = __half22float2(vh[1]);
            ffma2(acc0, pk2(f01.x, f01.y), prd);
            ffma2(acc1, pk2(f23.x, f23.y), prd);
        }
    }
    const float rinv = __frcp_rn(l);
    float o[4];
    unpk2(acc0, o[0], o[1]);
    unpk2(acc1, o[2], o[3]);

    const int c = BR * 64 + head * HEADD + sl * 4;
    __nv_bfloat16 hi[4], lo[4];
    #pragma unroll
    for (int i = 0; i < 4; i++) {
        const float v = o[i] * rinv;
        hi[i] = __float2bfloat16(v);
        lo[i] = __float2bfloat16(v - __bfloat162float(hi[i]));
    }
    __nv_bfloat16* yr = g_ye + (size_t)pix * KEXT;
    *(u64*)(yr + c)       = *(const u64*)hi;
    *(u64*)(yr + 192 + c) = *(const u64*)lo;
}

#define ABLOCKS (NPIX * HEADSB / 32)   // 2048 blocks per branch

__global__ __launch_bounds__(256) void natten_all(const float* __restrict__ rpb0,
                                                  const float* __restrict__ rpb1,
                                                  const float* __restrict__ rpb2) {
    __shared__ float srpb[338];        // up to 2*13*13
    const int br  = blockIdx.x % 3;    // stripe branches across SMs
    const int idx = blockIdx.x / 3;
    if (br == 0)      natten_body<3, 1, 0>(rpb0, idx, srpb);
    else if (br == 1) natten_body<5, 2, 1>(rpb1, idx, srpb);
    else              natten_body<7, 3, 2>(rpb2, idx, srpb);
}

// ---------------------------------------------------------------------------
extern "C" void kernel_launch(void* const* d_in, const int* in_sizes, int n_in,
                              void* d_out, int out_size) {
    const float* x      = (const float*)d_in[0];
    const float* qkv_w  = (const float*)d_in[1];
    const float* qkv_b  = (const float*)d_in[2];
    const float* proj_w = (const float*)d_in[3];
    const float* proj_b = (const float*)d_in[4];
    const float* rpb0   = (const float*)d_in[5];
    const float* rpb1   = (const float*)d_in[6];
    const float* rpb2   = (const float*)d_in[7];
    float* out = (float*)d_out;

    static bool init_done = false;
    if (!init_done) {
        cudaFuncSetAttribute(hmma_gemm<0>, cudaFuncAttributeMaxDynamicSharedMemorySize, SM_TOT);
        cudaFuncSetAttribute(hmma_gemm<1>, cudaFuncAttributeMaxDynamicSharedMemorySize, SM_TOT);
        init_done = true;
    }

    __nv_bfloat16* xe  = nullptr; cudaGetSymbolAddress((void**)&xe,  g_xe);
    __nv_bfloat16* ye  = nullptr; cudaGetSymbolAddress((void**)&ye,  g_ye);
    __nv_bfloat16* wqe = nullptr; cudaGetSymbolAddress((void**)&wqe, g_wqe);
    __nv_bfloat16* wpe = nullptr; cudaGetSymbolAddress((void**)&wpe, g_wpe);

    conv_all<<<6720, 256>>>(x, qkv_w, proj_w);

    hmma_gemm<0><<<dim3(NPIX / MT, QKVN / NT), 256, SM_TOT>>>(xe, wqe, qkv_b, nullptr);

    natten_all<<<3 * ABLOCKS, 256>>>(rpb0, rpb1, rpb2);

    hmma_gemm<1><<<dim3(NPIX / MT, DIM / NT), 256, SM_TOT>>>(ye, wpe, proj_b, out);
}

// round 14
// speedup vs baseline: 1.2022x; 1.0416x over previous
#include <cuda_runtime.h>
#include <cuda_bf16.h>
#include <cuda_fp16.h>
#include <cstdint>

#define BB     8
#define HH     64
#define WW     64
#define NPIX   32768
#define DIM    192
#define QKVN   576
#define HEADSB 2
#define HEADD  32
#define KEXT   384        // hi(192) | lo(192) bf16

typedef unsigned long long u64;
typedef unsigned int u32;

// Scratch (device globals: allocation-free rule)
__device__ float         g_q[(size_t)NPIX * DIM];          // pre-scaled q, [pix][192]
__device__ __half        g_k[(size_t)3 * NPIX * 64];       // [branch][pix][64] fp16
__device__ __half        g_v[(size_t)3 * NPIX * 64];       // [branch][pix][64] fp16
__device__ __nv_bfloat16 g_xe[(size_t)NPIX * KEXT];
__device__ __nv_bfloat16 g_ye[(size_t)NPIX * KEXT];
__device__ __nv_bfloat16 g_wqe[(size_t)QKVN * KEXT];
__device__ __nv_bfloat16 g_wpe[(size_t)DIM * KEXT];

// ---- f32x2 helpers ---------------------------------------------------------
__device__ __forceinline__ void ffma2(u64& d, u64 a, u64 b) {
    asm("fma.rn.f32x2 %0, %1, %2, %0;" : "+l"(d) : "l"(a), "l"(b));
}
__device__ __forceinline__ u64 dup2(float v) {
    u64 r; asm("mov.b64 %0, {%1, %1};" : "=l"(r) : "f"(v)); return r;
}
__device__ __forceinline__ u64 pk2(float lo, float hi) {
    u64 r; asm("mov.b64 %0, {%1, %2};" : "=l"(r) : "f"(lo), "f"(hi)); return r;
}
__device__ __forceinline__ void unpk2(u64 v, float& lo, float& hi) {
    asm("mov.b64 {%0, %1}, %2;" : "=f"(lo), "=f"(hi) : "l"(v));
}
__device__ __forceinline__ u32 sToU32(const void* p) {
    u32 a;
    asm("{ .reg .u64 t; cvta.to.shared.u64 t, %1; cvt.u32.u64 %0, t; }" : "=r"(a) : "l"(p));
    return a;
}

// ---- warp MMA primitives ----------------------------------------------------
#define LDSM4(r, addr) \
    asm volatile("ldmatrix.sync.aligned.m8n8.x4.shared.b16 {%0,%1,%2,%3}, [%4];" \
                 : "=r"((r)[0]), "=r"((r)[1]), "=r"((r)[2]), "=r"((r)[3]) : "r"(addr))

__device__ __forceinline__ void hmma(float* c, const u32* a, u32 b0, u32 b1) {
    asm volatile(
        "mma.sync.aligned.m16n8k16.row.col.f32.bf16.bf16.f32 "
        "{%0,%1,%2,%3}, {%4,%5,%6,%7}, {%8,%9}, {%0,%1,%2,%3};"
        : "+f"(c[0]), "+f"(c[1]), "+f"(c[2]), "+f"(c[3])
        : "r"(a[0]), "r"(a[1]), "r"(a[2]), "r"(a[3]), "r"(b0), "r"(b1));
}

#define CPA16(s, g)  asm volatile("cp.async.cg.shared.global [%0], [%1], 16;" :: "r"(s), "l"(g))
#define CPA_COMMIT() asm volatile("cp.async.commit_group;" ::: "memory")
#define CPA_WAITN(n) asm volatile("cp.async.wait_group %0;" :: "n"(n) : "memory")

// ---------------------------------------------------------------------------
// conv_all: merged conv_x (blocks 0..6143) + conv_w (blocks 6144..6719)
// ---------------------------------------------------------------------------
__global__ __launch_bounds__(256) void conv_all(const float* __restrict__ x,
                                                const float* __restrict__ wq,
                                                const float* __restrict__ wp) {
    const int bb = blockIdx.x;
    if (bb < 6144) {
        __shared__ float t[32][33];
        const int tx = threadIdx.x & 31, ty = threadIdx.x >> 5;
        const int s0 = (bb & 127) * 32;
        const int k0 = ((bb >> 7) % 6) * 32;
        const int b  = bb / 768;
        const float* xb = x + ((size_t)b * DIM + k0) * 4096 + s0;
        #pragma unroll
        for (int r = 0; r < 4; r++)
            t[ty + 8 * r][tx] = xb[(size_t)(ty + 8 * r) * 4096 + tx];
        __syncthreads();
        #pragma unroll
        for (int r = 0; r < 4; r++) {
            const int sl = ty + 8 * r;
            const float v = t[tx][sl];
            const __nv_bfloat16 h = __float2bfloat16(v);
            const __nv_bfloat16 l = __float2bfloat16(v - __bfloat162float(h));
            __nv_bfloat16* row = g_xe + (size_t)((b << 12) + s0 + sl) * KEXT;
            row[k0 + tx]       = h;
            row[192 + k0 + tx] = l;
        }
    } else {
        int i = (bb - 6144) * 256 + threadIdx.x;
        if (i < QKVN * DIM) {
            const int n = i / DIM, k = i % DIM;
            const float v = wq[i];
            const __nv_bfloat16 h = __float2bfloat16(v);
            const __nv_bfloat16 l = __float2bfloat16(v - __bfloat162float(h));
            g_wqe[(size_t)n * KEXT + k] = h;
            g_wqe[(size_t)n * KEXT + 192 + k] = l;
        } else {
            i -= QKVN * DIM;
            if (i < DIM * DIM) {
                const int n = i / DIM, k = i % DIM;
                const float v = wp[i];
                const __nv_bfloat16 h = __float2bfloat16(v);
                const __nv_bfloat16 l = __float2bfloat16(v - __bfloat162float(h));
                g_wpe[(size_t)n * KEXT + k] = h;
                g_wpe[(size_t)n * KEXT + 192 + k] = l;
            }
        }
    }
}

// ---------------------------------------------------------------------------
// HMMA GEMM, CTA 128x64, 8 warps (4m x 2n), extended-K split.
// B resident (48 KB); A streamed in 6 octs of 16 KB via 4-slot ring (64 KB).
// 112 KB smem -> 2 CTAs/SM. EPI=0: routed q/k/v stores.  EPI=1: CHW out.
// ---------------------------------------------------------------------------
#define MT 128
#define NT 64
#define SM_B 0                      // B: 64 rows x 768 B = 49152
#define SM_A 49152                  // A ring: 4 x 16384
#define SM_TOT 114688

template<int EPI>
__global__ __launch_bounds__(256, 2) void hmma_gemm(const __nv_bfloat16* __restrict__ A,
                                                    const __nv_bfloat16* __restrict__ Bw,
                                                    const float* __restrict__ bias,
                                                    float* __restrict__ outp) {
    extern __shared__ char smem[];
    const u32 sb = sToU32(smem);
    const int tid = threadIdx.x;
    const int wid = tid >> 5, lane = tid & 31;
    const int m0 = blockIdx.x * MT;
    const int n0 = blockIdx.y * NT;

    const __nv_bfloat16* Ab = A + (size_t)m0 * KEXT;
    const __nv_bfloat16* Bb = Bw + (size_t)n0 * KEXT;

    // ---- prologue: B (48 KB, group0) then A octs 0..3 (16 KB each, groups 1-4)
    #pragma unroll
    for (int i = 0; i < 12; i++) {                       // B: 64 rows x 48 chunks
        const int idx = tid + i * 256;
        const int r = idx / 48, c = idx % 48;
        CPA16(sb + SM_B + r * 768 + ((c ^ (r & 7)) << 4), Bb + (size_t)r * KEXT + c * 8);
    }
    CPA_COMMIT();
    #pragma unroll
    for (int o = 0; o < 4; o++) {                        // A octs: 128 rows x 8 chunks
        #pragma unroll
        for (int i = 0; i < 4; i++) {
            const int idx = tid + i * 256;
            const int r = idx >> 3, c = idx & 7;
            CPA16(sb + SM_A + o * 16384 + r * 128 + ((c ^ (r & 7)) << 4),
                  Ab + (size_t)r * KEXT + (o * 8 + c) * 8);
        }
        CPA_COMMIT();
    }

    const int warpM = (wid >> 1) * 32;
    const int warpN = (wid & 1) * 32;
    const int lr = lane & 15;
    const int lh = lane >> 4;
    const int asw = lr & 7;
    u32 bBase[2]; int bsw[2];
    #pragma unroll
    for (int g = 0; g < 2; g++) {
        const int row = warpN + g * 16 + lr;
        bBase[g] = sb + SM_B + row * 768;
        bsw[g]   = row & 7;
    }

    float acc[2][4][4] = {};

    #pragma unroll
    for (int st = 0; st < 6; st++) {
        if (st < 3) { CPA_WAITN(3); }
        else if (st == 3) { CPA_WAITN(2); }
        else if (st == 4) { CPA_WAITN(1); }
        else { CPA_WAITN(0); }
        __syncthreads();

        const int slot = st & 3;
        const u32 aB = sb + SM_A + slot * 16384 + (warpM + lr) * 128;
        const int nk = (st < 3) ? 8 : 4;
        #pragma unroll
        for (int kk = 0; kk < 8; kk++) {
            if (kk >= nk) break;
            const int boct = (st < 3) ? ((kk < 4) ? st : st + 3) : (st - 3);
            const int al = kk & 3;
            u32 af0[4], af1[4];
            LDSM4(af0, aB + (((al * 2 + lh) ^ asw) << 4));
            LDSM4(af1, aB + 16 * 128 + (((al * 2 + lh) ^ asw) << 4));
            const int bc = boct * 8 + al * 2 + lh;
            u32 bf[2][4];
            #pragma unroll
            for (int g = 0; g < 2; g++)
                LDSM4(bf[g], bBase[g] + ((bc ^ bsw[g]) << 4));
            #pragma unroll
            for (int j = 0; j < 4; j++) {
                const int g = j >> 1, p = j & 1;
                hmma(acc[0][j], af0, bf[g][p], bf[g][p + 2]);
                hmma(acc[1][j], af1, bf[g][p], bf[g][p + 2]);
            }
        }
        __syncthreads();
        if (st < 2) {
            #pragma unroll
            for (int i = 0; i < 4; i++) {
                const int idx = tid + i * 256;
                const int r = idx >> 3, c = idx & 7;
                CPA16(sb + SM_A + slot * 16384 + r * 128 + ((c ^ (r & 7)) << 4),
                      Ab + (size_t)r * KEXT + ((st + 4) * 8 + c) * 8);
            }
            CPA_COMMIT();
        }
    }

    // ---- epilogue (smem reuse)
    if (EPI == 0) {
        float* Ct = (float*)smem;   // [128][68]
        #pragma unroll
        for (int mt = 0; mt < 2; mt++) {
            #pragma unroll
            for (int j = 0; j < 4; j++) {
                const int rm = warpM + mt * 16 + (lane >> 2);
                const int rn = warpN + j * 8 + (lane & 3) * 2;
                Ct[rm * 68 + rn]           = acc[mt][j][0];
                Ct[rm * 68 + rn + 1]       = acc[mt][j][1];
                Ct[(rm + 8) * 68 + rn]     = acc[mt][j][2];
                Ct[(rm + 8) * 68 + rn + 1] = acc[mt][j][3];
            }
        }
        __syncthreads();
        // whole 64-wide tile maps to one section: q (sec 0), k (1), or v (2)
        const int br = n0 / 192, rr = n0 % 192, sec = rr >> 6;
        #pragma unroll
        for (int i = 0; i < 8; i++) {
            const int idx = tid + i * 256;          // 2048 stores
            const int m = idx >> 4, c = (idx & 15) * 4;
            const float4 bv = *(const float4*)&bias[n0 + c];
            float4 v;
            v.x = Ct[m * 68 + c]     + bv.x;
            v.y = Ct[m * 68 + c + 1] + bv.y;
            v.z = Ct[m * 68 + c + 2] + bv.z;
            v.w = Ct[m * 68 + c + 3] + bv.w;
            const size_t pix = m0 + m;
            if (sec == 0) {
                const float qsc = 0.17677669529663687f;
                v.x *= qsc; v.y *= qsc; v.z *= qsc; v.w *= qsc;
                *(float4*)&g_q[pix * DIM + br * 64 + c] = v;
            } else {
                __half2 h0 = __float22half2_rn(make_float2(v.x, v.y));
                __half2 h1 = __float22half2_rn(make_float2(v.z, v.w));
                __half* dst = (sec == 1) ? g_k : g_v;
                __half2* vp = (__half2*)&dst[((size_t)(br << 15) + pix) * 64 + c];
                vp[0] = h0; vp[1] = h1;
            }
        }
    } else {
        float* Ct = (float*)smem;   // [64][132] transposed
        #pragma unroll
        for (int mt = 0; mt < 2; mt++) {
            #pragma unroll
            for (int j = 0; j < 4; j++) {
                const int rn = warpN + j * 8 + (lane & 3) * 2;
                const int rm = warpM + mt * 16 + (lane >> 2);
                Ct[rn * 132 + rm]           = acc[mt][j][0];
                Ct[(rn + 1) * 132 + rm]     = acc[mt][j][1];
                Ct[rn * 132 + rm + 8]       = acc[mt][j][2];
                Ct[(rn + 1) * 132 + rm + 8] = acc[mt][j][3];
            }
        }
        __syncthreads();
        const int b = m0 >> 12, s0 = m0 & 4095;
        float* ob = outp + ((size_t)b * DIM + n0) * 4096 + s0;
        #pragma unroll
        for (int i = 0; i < 32; i++) {
            const int idx = tid + i * 256;
            const int n = idx >> 7, m = idx & 127;
            ob[(size_t)n * 4096 + m] = Ct[n * 132 + m] + bias[n0 + n];
        }
    }
}

// ---------------------------------------------------------------------------
// NATTEN: 8 lanes per (pixel, head); k,v fp16 (fp32 math); rpb in smem;
// k+v rows loaded together; max-free softmax. Output split bf16 into g_ye.
// ---------------------------------------------------------------------------
template<int K, int D, int BR>
__device__ __forceinline__ void natten_body(const float* __restrict__ rpb, int blk,
                                            float* __restrict__ srpb) {
    for (int i = threadIdx.x; i < 2 * (2 * K - 1) * (2 * K - 1); i += 256)
        srpb[i] = rpb[i];
    __syncthreads();

    const int sl   = threadIdx.x & 7;
    const int gid  = (blk * 256 + threadIdx.x) >> 3;
    const int head = gid & 1;
    const int pix  = gid >> 1;
    const int w = pix & 63;
    const int h = (pix >> 6) & 63;
    const int b = pix >> 12;

    const float4 q = *(const float4*)&g_q[(size_t)pix * DIM + BR * 64 + head * HEADD + sl * 4];

    const int gh = h % D, iih = h / D;
    const int Lgh = (HH - gh + D - 1) / D;
    const int sth = min(max(iih - K / 2, 0), Lgh - K);
    const int gw = w % D, iiw = w / D;
    const int Lgw = (WW - gw + D - 1) / D;
    const int stw = min(max(iiw - K / 2, 0), Lgw - K);

    const float* rpbh = srpb + head * (2 * K - 1) * (2 * K - 1)
                       + (sth - iih + K - 1) * (2 * K - 1)
                       + (stw - iiw + K - 1);

    const size_t nb0 = (size_t)(BR << 15) + (b << 12) + (gh + sth * D) * 64 + (gw + stw * D);
    const __half* kbase = g_k + nb0 * 64 + head * HEADD + sl * 4;
    const __half* vbase = g_v + nb0 * 64 + head * HEADD + sl * 4;

    const int strideWk = D * 64;            // elems per kw step
    const int strideHk = D * 64 * 64;

    float l = 0.f;
    u64 acc0 = 0, acc1 = 0;

    #pragma unroll
    for (int kh = 0; kh < K; kh++) {
        const __half* pk = kbase + (size_t)kh * strideHk;
        const __half* pv = vbase + (size_t)kh * strideHk;
        float sarr[K];
        u64 varr[K];                        // 4 halves each
        #pragma unroll
        for (int kw = 0; kw < K; kw++) {
            const u64 k4p = *(const u64*)(pk + (size_t)kw * strideWk);
            varr[kw] = *(const u64*)(pv + (size_t)kw * strideWk);
            const __half2* kh2 = (const __half2*)&k4p;
            const float2 k01 = __half22float2(kh2[0]);
            const float2 k23 = __half22float2(kh2[1]);
            sarr[kw] = q.x * k01.x + q.y * k01.y + q.z * k23.x + q.w * k23.y;
        }
        #pragma unroll
        for (int kw = 0; kw < K; kw++) {
            float s = sarr[kw];
            s += __shfl_xor_sync(0xffffffffu, s, 4);
            s += __shfl_xor_sync(0xffffffffu, s, 2);
            s += __shfl_xor_sync(0xffffffffu, s, 1);
            sarr[kw] = __expf(s + rpbh[kh * (2 * K - 1) + kw]);
        }
        #pragma unroll
        for (int kw = 0; kw < K; kw++) {
            const float pr = sarr[kw];
            l += pr;
            const u64 prd = dup2(pr);
            const __half2* vh = (const __half2*)&varr[kw];
            const float2 f01 = __half22float2(vh[0]);
            const float2 f23 = __half22float2(vh[1]);
            ffma2(acc0, pk2(f01.x, f01.y), prd);
            ffma2(acc1, pk2(f23.x, f23.y), prd);
        }
    }
    const float rinv = __frcp_rn(l);
    float o[4];
    unpk2(acc0, o[0], o[1]);
    unpk2(acc1, o[2], o[3]);

    const int c = BR * 64 + head * HEADD + sl * 4;
    __nv_bfloat16 hi[4], lo[4];
    #pragma unroll
    for (int i = 0; i < 4; i++) {
        const float v = o[i] * rinv;
        hi[i] = __float2bfloat16(v);
        lo[i] = __float2bfloat16(v - __bfloat162float(hi[i]));
    }
    __nv_bfloat16* yr = g_ye + (size_t)pix * KEXT;
    *(u64*)(yr + c)       = *(const u64*)hi;
    *(u64*)(yr + 192 + c) = *(const u64*)lo;
}

#define ABLOCKS (NPIX * HEADSB / 32)   // 2048 blocks per branch

__global__ __launch_bounds__(256) void natten_all(const float* __restrict__ rpb0,
                                                  const float* __restrict__ rpb1,
                                                  const float* __restrict__ rpb2) {
    __shared__ float srpb[338];        // up to 2*13*13
    const int br  = blockIdx.x % 3;    // stripe branches across SMs
    const int idx = blockIdx.x / 3;
    if (br == 0)      natten_body<3, 1, 0>(rpb0, idx, srpb);
    else if (br == 1) natten_body<5, 2, 1>(rpb1, idx, srpb);
    else              natten_body<7, 3, 2>(rpb2, idx, srpb);
}

// ---------------------------------------------------------------------------
extern "C" void kernel_launch(void* const* d_in, const int* in_sizes, int n_in,
                              void* d_out, int out_size) {
    const float* x      = (const float*)d_in[0];
    const float* qkv_w  = (const float*)d_in[1];
    const float* qkv_b  = (const float*)d_in[2];
    const float* proj_w = (const float*)d_in[3];
    const float* proj_b = (const float*)d_in[4];
    const float* rpb0   = (const float*)d_in[5];
    const float* rpb1   = (const float*)d_in[6];
    const float* rpb2   = (const float*)d_in[7];
    float* out = (float*)d_out;

    static bool init_done = false;
    if (!init_done) {
        cudaFuncSetAttribute(hmma_gemm<0>, cudaFuncAttributeMaxDynamicSharedMemorySize, SM_TOT);
        cudaFuncSetAttribute(hmma_gemm<1>, cudaFuncAttributeMaxDynamicSharedMemorySize, SM_TOT);
        init_done = true;
    }

    __nv_bfloat16* xe  = nullptr; cudaGetSymbolAddress((void**)&xe,  g_xe);
    __nv_bfloat16* ye  = nullptr; cudaGetSymbolAddress((void**)&ye,  g_ye);
    __nv_bfloat16* wqe = nullptr; cudaGetSymbolAddress((void**)&wqe, g_wqe);
    __nv_bfloat16* wpe = nullptr; cudaGetSymbolAddress((void**)&wpe, g_wpe);

    conv_all<<<6720, 256>>>(x, qkv_w, proj_w);

    hmma_gemm<0><<<dim3(NPIX / MT, QKVN / NT), 256, SM_TOT>>>(xe, wqe, qkv_b, nullptr);

    natten_all<<<3 * ABLOCKS, 256>>>(rpb0, rpb1, rpb2);

    hmma_gemm<1><<<dim3(NPIX / MT, DIM / NT), 256, SM_TOT>>>(ye, wpe, proj_b, out);
}